// round 14
// baseline (speedup 1.0000x reference)
#include <cuda_runtime.h>
#include <cstdint>

#define B_ 256
#define T_ 512
#define C_ 256
#define L_ 64

__device__ float g_loss[B_];
__device__ unsigned int g_ctr = 0;

// Named barriers, runtime id, count = 288 (one 9-warp group).
__device__ __forceinline__ void bar_sync288(int id) {
  asm volatile("bar.sync %0, 288;" :: "r"(id) : "memory");
}
__device__ __forceinline__ void bar_arrive288(int id) {
  asm volatile("bar.arrive %0, 288;" :: "r"(id) : "memory");
}

// ---------------------------------------------------------------------------
// Fused CTC kernel, TWO batch rows per block (576 thr = 2 independent 9-warp
// groups) so grid = 128 <= 148 SMs -> single wave (R13 was exactly 2 waves).
// Each group: warps 0-7 produce (LDG->reg 2-phase lookahead, softmax, write
// compressed row [eb*256 | p_odd*mask*256] into a 4-slot ring), warp 8 runs
// the CTC recurrence (4 states/lane + s=128 on lane 31, 1 shfl/step, 2^8
// pre-scale, pipelined power-of-2 renorm). Group g uses named barriers
// 8g+0..8g+3 (FULL) / 8g+4..8g+7 (EMPTY); no __syncthreads anywhere.
// Batch mean folded in via atomic ticket (replay-safe reset).
// ---------------------------------------------------------------------------
__global__ void __launch_bounds__(576) ctc_fused_kernel(
    const float* __restrict__ logits,
    const int* __restrict__ targets,
    const int* __restrict__ input_lengths,
    const int* __restrict__ target_lengths,
    float* __restrict__ out) {
  __shared__ float ring[2][4][8][68];   // [group][slot][prow][state]
  __shared__ float scratch[16][C_];     // per-producer-warp exp scratch
  __shared__ int   stg[2][L_];
  __shared__ float shf[2][132];

  int tid = threadIdx.x;
  int wid = tid >> 5, lane = tid & 31;
  int g   = (wid >= 9) ? 1 : 0;
  int lw  = wid - 9 * g;                // 0..8 within group
  int ltid = tid - g * 288;
  int b = 2 * blockIdx.x + g;
  int len = input_lengths[b];
  int tl  = target_lengths[b];
  int Sb  = 2 * tl + 1;
  int base = g * 8;                     // barrier id base for this group

  if (ltid < L_) stg[g][ltid] = targets[b * L_ + ltid];
  bar_sync288(base + 4);                // one-shot full sync on EMPTY0

  const float* lg = logits + (size_t)b * T_ * C_;
  const int* stgg = stg[g];
  float (*ringg)[8][68] = ring[g];

  if (lw < 8) {
    // ---------------- producers ----------------
    int t0l = stgg[2 * lane], t1l = stgg[2 * lane + 1];
    float c1m = (4 * lane + 1 < Sb) ? 256.f : 0.f;
    float c3m = (4 * lane + 3 < Sb) ? 256.f : 0.f;
    float* scr = scratch[g * 8 + lw];

#define LOADPH(PH, RA, RB)                                                 \
    do {                                                                   \
      int r_ = (PH) * 8 + lw; r_ = r_ < T_ ? r_ : T_ - 1;                  \
      const float4* p_ = (const float4*)(lg + (size_t)r_ * C_);            \
      (RA) = p_[lane]; (RB) = p_[lane + 32];                               \
    } while (0)

#define PRODUCE(VA, VB, SLOT)                                              \
    do {                                                                   \
      float4 eA, eB;                                                       \
      eA.x = __expf((VA).x); eA.y = __expf((VA).y);                        \
      eA.z = __expf((VA).z); eA.w = __expf((VA).w);                        \
      eB.x = __expf((VB).x); eB.y = __expf((VB).y);                        \
      eB.z = __expf((VB).z); eB.w = __expf((VB).w);                        \
      float s = ((eA.x + eA.y) + (eA.z + eA.w)) +                          \
                ((eB.x + eB.y) + (eB.z + eB.w));                           \
      _Pragma("unroll")                                                    \
      for (int o = 16; o; o >>= 1) s += __shfl_xor_sync(0xffffffffu, s, o);\
      float inv = __frcp_rn(s);                                            \
      ((float4*)scr)[lane]      = eA;                                      \
      ((float4*)scr)[lane + 32] = eB;                                      \
      __syncwarp();                                                        \
      float2 o2;                                                           \
      o2.x = scr[t0l] * inv * c1m;                                         \
      o2.y = scr[t1l] * inv * c3m;                                         \
      ((float2*)((SLOT) + 4))[lane] = o2;                                  \
      if (lane == 0) (SLOT)[0] = scr[0] * inv * 256.f;                     \
      __syncwarp();                                                        \
    } while (0)

    float4 aA, aB, cOA, cOB, cEA, cEB, nA, nB;
    // preamble: fill slots 0-3 (phases 0-3), staging 2 phases ahead
    LOADPH(0, aA, aB); LOADPH(1, cOA, cOB); LOADPH(2, cEA, cEB);
    PRODUCE(aA, aB, ringg[0][lw]);                    bar_arrive288(base + 0);
    LOADPH(3, nA, nB); PRODUCE(cOA, cOB, ringg[1][lw]);
    cOA = nA; cOB = nB;                               bar_arrive288(base + 1);
    LOADPH(4, nA, nB); PRODUCE(cEA, cEB, ringg[2][lw]);
    cEA = nA; cEB = nB;                               bar_arrive288(base + 2);
    LOADPH(5, nA, nB); PRODUCE(cOA, cOB, ringg[3][lw]);
    cOA = nA; cOB = nB;                               bar_arrive288(base + 3);

    for (int p = 4; p < 64; p += 4) {
      LOADPH(p + 2, nA, nB); bar_sync288(base + 4);
      PRODUCE(cEA, cEB, ringg[0][lw]); cEA = nA; cEB = nB; bar_arrive288(base + 0);
      LOADPH(p + 3, nA, nB); bar_sync288(base + 5);
      PRODUCE(cOA, cOB, ringg[1][lw]); cOA = nA; cOB = nB; bar_arrive288(base + 1);
      LOADPH(p + 4, nA, nB); bar_sync288(base + 6);
      PRODUCE(cEA, cEB, ringg[2][lw]); cEA = nA; cEB = nB; bar_arrive288(base + 2);
      LOADPH(p + 5, nA, nB); bar_sync288(base + 7);
      PRODUCE(cOA, cOB, ringg[3][lw]); cOA = nA; cOB = nB; bar_arrive288(base + 3);
    }
#undef LOADPH
#undef PRODUCE
  } else {
    // ---------------- consumer (warp 8 of group) ----------------
    int t0l = stgg[2 * lane], t1l = stgg[2 * lane + 1];
    float skip1 = 0.f, skip3 = (t1l != t0l) ? 1.f : 0.f;
    if (lane > 0) skip1 = (t0l != stgg[2 * lane - 1]) ? 1.f : 0.f;
    float c0 = (lane > 0 && 4 * lane < Sb) ? 1.f : 0.f;

    float a0 = 0.f, a1 = 0.f, a2 = 0.f, a3 = 0.f, a4 = 0.f;
    int e_total = 0, epend = 0;
    float fpend = 1.f;

#define CTC_STEP(EB, PL)                                                   \
    do {                                                                   \
      float u1 = __shfl_up_sync(0xffffffffu, a3, 1);                       \
      float n0 = fmaf(u1, c0, a0) * (EB);                                  \
      float n1 = fmaf(skip1, u1, a1 + a0) * (PL).x;                        \
      float n2 = (a2 + a1) * (EB);                                         \
      float n3 = fmaf(skip3, a1, a3 + a2) * (PL).y;                        \
      float n4 = (a4 + a3) * (EB);                                         \
      a0 = n0; a1 = n1; a2 = n2; a3 = n3; a4 = n4;                         \
    } while (0)

#define CTC_RENORM_PIPE()                                                  \
    do {                                                                   \
      a0 *= fpend; a1 *= fpend; a2 *= fpend; a3 *= fpend; a4 *= fpend;     \
      e_total += epend;                                                    \
      float lm = fmaxf(fmaxf(a0, a1), fmaxf(fmaxf(a2, a3), a4));           \
      unsigned mb = __reduce_max_sync(0xffffffffu, __float_as_uint(lm));   \
      epend = (mb != 0u) ? ((int)(mb >> 23) - 127) : 0;                    \
      fpend = __int_as_float((127 - epend) << 23);                         \
    } while (0)

#define CTC_PHASE(P, SLOT)                                                 \
    do {                                                                   \
      float(*buf)[68] = ringg[(SLOT)];                                     \
      float  ebv[8];                                                       \
      float2 plv[8];                                                       \
      _Pragma("unroll")                                                    \
      for (int u = 0; u < 8; u++) {                                        \
        ebv[u] = buf[u][0];                                                \
        plv[u] = ((float2*)(buf[u] + 4))[lane];                            \
      }                                                                    \
      _Pragma("unroll")                                                    \
      for (int u = 0; u < 8; u++) {                                        \
        int tt = (P) * 8 + u;                                              \
        if (tt == 0) {                                                     \
          if (lane == 0) {                                                 \
            a0 = ebv[0] * (1.f / 256.f);                                   \
            a1 = plv[0].x * (1.f / 256.f);                                 \
          }                                                                \
        } else if (tt < len) {                                             \
          CTC_STEP(ebv[u], plv[u]);                                        \
          if ((tt & 3) == 3) CTC_RENORM_PIPE();                            \
        }                                                                  \
      }                                                                    \
    } while (0)

    for (int p = 0; p < 60; p += 4) {
      bar_sync288(base + 0); CTC_PHASE(p + 0, 0); bar_arrive288(base + 4);
      bar_sync288(base + 1); CTC_PHASE(p + 1, 1); bar_arrive288(base + 5);
      bar_sync288(base + 2); CTC_PHASE(p + 2, 2); bar_arrive288(base + 6);
      bar_sync288(base + 3); CTC_PHASE(p + 3, 3); bar_arrive288(base + 7);
    }
    bar_sync288(base + 0); CTC_PHASE(60, 0);
    bar_sync288(base + 1); CTC_PHASE(61, 1);
    bar_sync288(base + 2); CTC_PHASE(62, 2);
    bar_sync288(base + 3); CTC_PHASE(63, 3);

    // per-row loss
    float* sf = shf[g];
    sf[4 * lane + 0] = a0;
    sf[4 * lane + 1] = a1;
    sf[4 * lane + 2] = a2;
    sf[4 * lane + 3] = a3;
    if (lane == 31) sf[128] = a4;
    __syncwarp();
    if (lane == 0) {
      float ssum = sf[2 * tl] + sf[2 * tl - 1];
      // a_true = a_stored * 2^(e_total - 8*(len-1))
      float loss = -(logf(ssum) +
                     (float)(e_total - 8 * (len - 1)) * 0.69314718055994530942f);
      if (!isfinite(loss) || loss > 1e20f) loss = 0.f;   // zero_infinity
      g_loss[b] = loss / (float)tl;
    }

    // fold the batch mean into the last-arriving consumer (replay-safe)
    __threadfence();
    unsigned tkt = 0;
    if (lane == 0) tkt = atomicAdd(&g_ctr, 1u);
    tkt = __shfl_sync(0xffffffffu, tkt, 0);
    if (tkt == B_ - 1) {
      __threadfence();
      float v = 0.f;
      #pragma unroll
      for (int j = 0; j < 8; j++) v += __ldcg(&g_loss[lane * 8 + j]);
      #pragma unroll
      for (int o = 16; o; o >>= 1) v += __shfl_xor_sync(0xffffffffu, v, o);
      if (lane == 0) {
        *out = v * (1.0f / (float)B_);
        atomicExch(&g_ctr, 0u);                        // reset for graph replay
      }
    }
#undef CTC_STEP
#undef CTC_RENORM_PIPE
#undef CTC_PHASE
  }
}

extern "C" void kernel_launch(void* const* d_in, const int* in_sizes, int n_in,
                              void* d_out, int out_size) {
  const float* logits         = (const float*)d_in[0];
  const int*   targets        = (const int*)d_in[1];
  const int*   input_lengths  = (const int*)d_in[2];
  const int*   target_lengths = (const int*)d_in[3];
  (void)in_sizes; (void)n_in; (void)out_size;

  ctc_fused_kernel<<<B_ / 2, 576>>>(logits, targets, input_lengths,
                                    target_lengths, (float*)d_out);
}